// round 6
// baseline (speedup 1.0000x reference)
#include <cuda_runtime.h>
#include <math.h>

#define T_SEQ  2048
#define NE     2048
#define NH     16
#define NG     4
#define HS     128
#define QKVD   3072
#define INTERD 5632
#define VOCABN 32000

// ---------------- scratch (device globals; no allocations) ----------------
__device__ float g_X[T_SEQ * NE];
__device__ float g_Nrm[T_SEQ * NE];
__device__ float g_QKV[T_SEQ * QKVD];
__device__ float g_Q[NH * T_SEQ * HS];
__device__ float g_K[NG * T_SEQ * HS];
__device__ float g_Vt[NG * HS * T_SEQ];          // V transposed: [g][d][t]
__device__ float g_S[(size_t)NH * T_SEQ * T_SEQ]; // per-head attn matrix (256 MB)
__device__ float g_Y[T_SEQ * NE];
__device__ float g_H1[T_SEQ * INTERD];
__device__ float g_H2[T_SEQ * INTERD];

// ---------------- generic NT SGEMM: C[z] = alpha * A[z] @ B[z/bdiv]^T (+RES) --
// BM=BN=128, BK=8, 256 threads, 8x8 micro-tile.
__global__ __launch_bounds__(256) void sgemm_nt(
    const float* __restrict__ A, const float* __restrict__ B,
    float* __restrict__ C, const float* __restrict__ RES,
    int M, int N, int K, int lda, int ldb, int ldc, float alpha,
    long sA, long sB, long sC, int bdiv)
{
    int z = blockIdx.z;
    A += (long)z * sA;
    B += (long)(z / bdiv) * sB;
    C += (long)z * sC;
    if (RES) RES += (long)z * sC;

    __shared__ float As[8][128];
    __shared__ float Bs[8][128];

    int tid  = threadIdx.x;
    int bm   = blockIdx.y * 128;
    int bn   = blockIdx.x * 128;
    int lrow = tid >> 1;            // 0..127
    int lcol = (tid & 1) << 2;      // 0 or 4

    const float* Ap = A + (long)(bm + lrow) * lda + lcol;
    const float* Bp = B + (long)(bn + lrow) * ldb + lcol;

    int m0 = (tid >> 4) << 3;
    int n0 = (tid & 15) << 3;

    float acc[8][8];
#pragma unroll
    for (int i = 0; i < 8; i++)
#pragma unroll
        for (int j = 0; j < 8; j++) acc[i][j] = 0.f;

    for (int k0 = 0; k0 < K; k0 += 8) {
        float4 a4 = *(const float4*)(Ap + k0);
        float4 b4 = *(const float4*)(Bp + k0);
        As[lcol + 0][lrow] = a4.x; As[lcol + 1][lrow] = a4.y;
        As[lcol + 2][lrow] = a4.z; As[lcol + 3][lrow] = a4.w;
        Bs[lcol + 0][lrow] = b4.x; Bs[lcol + 1][lrow] = b4.y;
        Bs[lcol + 2][lrow] = b4.z; Bs[lcol + 3][lrow] = b4.w;
        __syncthreads();
#pragma unroll
        for (int k = 0; k < 8; k++) {
            float ar[8], br[8];
            *(float4*)&ar[0] = *(const float4*)&As[k][m0];
            *(float4*)&ar[4] = *(const float4*)&As[k][m0 + 4];
            *(float4*)&br[0] = *(const float4*)&Bs[k][n0];
            *(float4*)&br[4] = *(const float4*)&Bs[k][n0 + 4];
#pragma unroll
            for (int i = 0; i < 8; i++)
#pragma unroll
                for (int j = 0; j < 8; j++)
                    acc[i][j] += ar[i] * br[j];
        }
        __syncthreads();
    }

#pragma unroll
    for (int i = 0; i < 8; i++) {
        long row = bm + m0 + i;
#pragma unroll
        for (int j = 0; j < 8; j += 4) {
            long off = row * (long)ldc + bn + n0 + j;
            float4 r;
            r.x = acc[i][j] * alpha; r.y = acc[i][j + 1] * alpha;
            r.z = acc[i][j + 2] * alpha; r.w = acc[i][j + 3] * alpha;
            if (RES) {
                float4 q = *(const float4*)(RES + off);
                r.x += q.x; r.y += q.y; r.z += q.z; r.w += q.w;
            }
            *(float4*)(C + off) = r;
        }
    }
}

// ---------------- pointwise kernels ----------------
__global__ void embed_k(const int* __restrict__ idx, const float* __restrict__ wte,
                        float* __restrict__ X)
{
    int t = blockIdx.x;
    int tok = idx[t];
    const float* src = wte + (long)tok * NE;
    for (int i = threadIdx.x; i < NE; i += 256)
        X[(long)t * NE + i] = src[i];
}

__global__ void rmsnorm_k(const float* __restrict__ X, const float* __restrict__ w,
                          float* __restrict__ O)
{
    int t = blockIdx.x;
    const float* x = X + (long)t * NE;
    float ss = 0.f;
    for (int i = threadIdx.x; i < NE; i += 256) { float v = x[i]; ss += v * v; }
    __shared__ float red[256];
    red[threadIdx.x] = ss; __syncthreads();
    for (int s = 128; s > 0; s >>= 1) {
        if (threadIdx.x < s) red[threadIdx.x] += red[threadIdx.x + s];
        __syncthreads();
    }
    float r = rsqrtf(red[0] / NE + 1e-5f);
    for (int i = threadIdx.x; i < NE; i += 256)
        O[(long)t * NE + i] = x[i] * r * w[i];
}

// RoPE + elu+1. blockIdx.y: 0..15 -> q head, 16..19 -> k group. thread d=0..63.
__global__ void rope_elu_k(const float* __restrict__ QKV, float* __restrict__ Q,
                           float* __restrict__ Kc)
{
    int t = blockIdx.x;
    int u = blockIdx.y;
    int d = threadIdx.x;
    int g, slot;
    float* out;
    if (u < NH) { g = u >> 2; slot = u & 3; out = Q + ((long)u * T_SEQ + t) * HS; }
    else        { g = u - NH; slot = 4;     out = Kc + ((long)g * T_SEQ + t) * HS; }
    const float* src = QKV + (long)t * QKVD + (g * 6 + slot) * HS;
    float x1 = src[d], x2 = src[d + 64];
    // theta = 10000^(-d/64); angle in fp64 (fp32 sin/cos at angle~2000 loses ~1e-4)
    double theta = exp(-(double)d * (9.210340371976184 / 64.0));
    double ang = (double)t * theta;
    float c = (float)cos(ang), s = (float)sin(ang);
    float o1 = x1 * c - x2 * s;
    float o2 = x1 * s + x2 * c;
    out[d]      = (o1 > 0.f) ? o1 + 1.f : expf(o1);
    out[d + 64] = (o2 > 0.f) ? o2 + 1.f : expf(o2);
}

__global__ void copy_v_k(const float* __restrict__ QKV, float* __restrict__ Vt)
{
    int t = blockIdx.x, g = blockIdx.y, d = threadIdx.x;
    Vt[((long)g * HS + d) * T_SEQ + t] = QKV[(long)t * QKVD + (g * 6 + 5) * HS + d];
}

// masked row-normalize: row[s] = (s<=t) ? row[s]/(sum_{s<=t} row + 1e-8) : 0
__global__ void attn_norm_k(float* __restrict__ S)
{
    int t = blockIdx.x;
    int h = blockIdx.y;
    float* row = S + (size_t)h * T_SEQ * T_SEQ + (long)t * T_SEQ;
    float sum = 0.f;
    for (int s = threadIdx.x; s <= t; s += 256) sum += row[s];
    __shared__ float red[256];
    red[threadIdx.x] = sum; __syncthreads();
    for (int s = 128; s > 0; s >>= 1) {
        if (threadIdx.x < s) red[threadIdx.x] += red[threadIdx.x + s];
        __syncthreads();
    }
    float inv = 1.f / (red[0] + 1e-8f);
    for (int s = threadIdx.x; s < T_SEQ; s += 256)
        row[s] = (s <= t) ? row[s] * inv : 0.f;
}

__global__ void silu_mul_k(float* __restrict__ H1, const float* __restrict__ H2)
{
    long i = (long)blockIdx.x * 256 + threadIdx.x;
    if (i < (long)T_SEQ * INTERD) {
        float a = H1[i];
        H1[i] = (a / (1.f + expf(-a))) * H2[i];
    }
}

// ---------------- driver ----------------
extern "C" void kernel_launch(void* const* d_in, const int* in_sizes, int n_in,
                              void* d_out, int out_size)
{
    const int*   idx      = (const int*)d_in[0];
    const float* wte      = (const float*)d_in[1];
    const float* attn_w   = (const float*)d_in[2];
    const float* proj_w   = (const float*)d_in[3];
    const float* w1       = (const float*)d_in[4];
    const float* w2       = (const float*)d_in[5];
    const float* w3       = (const float*)d_in[6];
    const float* norm1_w  = (const float*)d_in[7];
    const float* norm2_w  = (const float*)d_in[8];
    const float* ln_f_w   = (const float*)d_in[9];
    const float* lm_head  = (const float*)d_in[10];
    float* out = (float*)d_out;

    float *X, *Nn, *QKV, *Q, *K, *Vt, *S, *Y, *H1, *H2;
    cudaGetSymbolAddress((void**)&X,   g_X);
    cudaGetSymbolAddress((void**)&Nn,  g_Nrm);
    cudaGetSymbolAddress((void**)&QKV, g_QKV);
    cudaGetSymbolAddress((void**)&Q,   g_Q);
    cudaGetSymbolAddress((void**)&K,   g_K);
    cudaGetSymbolAddress((void**)&Vt,  g_Vt);
    cudaGetSymbolAddress((void**)&S,   g_S);
    cudaGetSymbolAddress((void**)&Y,   g_Y);
    cudaGetSymbolAddress((void**)&H1,  g_H1);
    cudaGetSymbolAddress((void**)&H2,  g_H2);

    const float scale = 1.f / sqrtf((float)HS);

    embed_k<<<T_SEQ, 256>>>(idx, wte, X);

    for (int l = 0; l < 2; l++) {
        rmsnorm_k<<<T_SEQ, 256>>>(X, norm1_w + (long)l * NE, Nn);

        // qkv = n1 @ attn_w^T   (2048 x 3072)
        sgemm_nt<<<dim3(QKVD / 128, T_SEQ / 128, 1), 256>>>(
            Nn, attn_w + (long)l * QKVD * NE, QKV, nullptr,
            T_SEQ, QKVD, NE, NE, NE, QKVD, 1.f, 0, 0, 0, 1);

        rope_elu_k<<<dim3(T_SEQ, NH + NG), 64>>>(QKV, Q, K);
        copy_v_k<<<dim3(T_SEQ, NG), 128>>>(QKV, Vt);

        // S[h] = scale * Q[h] @ K[h/4]^T  (batched over 16 heads)
        sgemm_nt<<<dim3(T_SEQ / 128, T_SEQ / 128, NH), 256>>>(
            Q, K, S, nullptr,
            T_SEQ, T_SEQ, HS, HS, HS, T_SEQ, scale,
            (long)T_SEQ * HS, (long)T_SEQ * HS, (long)T_SEQ * T_SEQ, 4);

        attn_norm_k<<<dim3(T_SEQ, NH), 256>>>(S);

        // Y[:, h*128:(h+1)*128] = S[h] @ Vt[h/4]^T
        sgemm_nt<<<dim3(1, T_SEQ / 128, NH), 256>>>(
            S, Vt, Y, nullptr,
            T_SEQ, HS, T_SEQ, T_SEQ, T_SEQ, NE, 1.f,
            (long)T_SEQ * T_SEQ, (long)HS * T_SEQ, (long)HS, 4);

        // X += Y @ proj^T
        sgemm_nt<<<dim3(NE / 128, T_SEQ / 128, 1), 256>>>(
            Y, proj_w + (long)l * NE * NE, X, X,
            T_SEQ, NE, NE, NE, NE, NE, 1.f, 0, 0, 0, 1);

        rmsnorm_k<<<T_SEQ, 256>>>(X, norm2_w + (long)l * NE, Nn);

        sgemm_nt<<<dim3(INTERD / 128, T_SEQ / 128, 1), 256>>>(
            Nn, w1 + (long)l * INTERD * NE, H1, nullptr,
            T_SEQ, INTERD, NE, NE, NE, INTERD, 1.f, 0, 0, 0, 1);
        sgemm_nt<<<dim3(INTERD / 128, T_SEQ / 128, 1), 256>>>(
            Nn, w2 + (long)l * INTERD * NE, H2, nullptr,
            T_SEQ, INTERD, NE, NE, NE, INTERD, 1.f, 0, 0, 0, 1);

        silu_mul_k<<<(int)(((long)T_SEQ * INTERD + 255) / 256), 256>>>(H1, H2);

        // X += H @ w3^T
        sgemm_nt<<<dim3(NE / 128, T_SEQ / 128, 1), 256>>>(
            H1, w3 + (long)l * NE * INTERD, X, X,
            T_SEQ, NE, INTERD, INTERD, INTERD, NE, 1.f, 0, 0, 0, 1);
    }

    rmsnorm_k<<<T_SEQ, 256>>>(X, ln_f_w, Nn);

    // logits = x @ lm_head^T  (2048 x 32000)
    sgemm_nt<<<dim3(VOCABN / 128, T_SEQ / 128, 1), 256>>>(
        Nn, lm_head, out, nullptr,
        T_SEQ, VOCABN, NE, NE, NE, VOCABN, 1.f, 0, 0, 0, 1);
}

// round 10
// speedup vs baseline: 2.4509x; 2.4509x over previous
#include <cuda_runtime.h>
#include <cuda_bf16.h>
#include <stdint.h>
#include <math.h>

#define T_SEQ  2048
#define NE     2048
#define NH     16
#define NG     4
#define HS     128
#define QKVD   3072
#define INTERD 5632
#define VOCABN 32000

typedef __nv_bfloat16 bf16;

// ---------------- scratch (device globals; no allocations) ----------------
__device__ float g_X[T_SEQ * NE];
__device__ float g_QKV[T_SEQ * QKVD];
__device__ float g_S[(size_t)NH * T_SEQ * T_SEQ];   // fp32 attn scores (256 MB)
__device__ float g_Y[T_SEQ * NE];
__device__ float g_H1[T_SEQ * INTERD];
__device__ float g_H2[T_SEQ * INTERD];

// bf16 hi/lo operand buffers
__device__ bf16 g_Nh[T_SEQ * NE],            g_Nl[T_SEQ * NE];
__device__ bf16 g_Wh[(size_t)VOCABN * NE],   g_Wl[(size_t)VOCABN * NE];
__device__ bf16 g_Qh[NH * T_SEQ * HS],       g_Ql[NH * T_SEQ * HS];
__device__ bf16 g_Kh[NG * T_SEQ * HS],       g_Kl[NG * T_SEQ * HS];
__device__ bf16 g_Vh[NG * HS * T_SEQ],       g_Vl[NG * HS * T_SEQ];
__device__ bf16 g_Sh[(size_t)NH * T_SEQ * T_SEQ], g_Sl[(size_t)NH * T_SEQ * T_SEQ];
__device__ bf16 g_Yh[T_SEQ * NE],            g_Yl[T_SEQ * NE];
__device__ bf16 g_Hh[T_SEQ * INTERD],        g_Hl[T_SEQ * INTERD];

// rope tables
__device__ float g_cos[T_SEQ * 64];
__device__ float g_sin[T_SEQ * 64];

__device__ __forceinline__ void split2(float x, bf16& h, bf16& l) {
    h = __float2bfloat16_rn(x);
    l = __float2bfloat16_rn(x - __bfloat162float(h));
}

// ================= split-bf16 tensor-core GEMM =================
// C[z] = alpha * (Ah+Al)[z] @ (Bh+Bl)[z/bdiv]^T (+RES), fp32 accum.
// Block 128x128, KT=32, 8 warps (2x4), warp tile 64x32, mma m16n8k16.
#define PAD 40
#define SA_H 0
#define SA_L 5120
#define SB_H 10240
#define SB_L 15360
#define STAGE_ELEMS 20480          // 4 * 128 * PAD
#define GEMM_SMEM (2 * STAGE_ELEMS * 2)   // 81920 bytes

#define LDSM4(R0,R1,R2,R3,ADDR) \
  asm volatile("ldmatrix.sync.aligned.m8n8.x4.shared.b16 {%0,%1,%2,%3}, [%4];" \
    : "=r"(R0),"=r"(R1),"=r"(R2),"=r"(R3) : "r"(ADDR))

#define MMA_B16(C,A,B) \
  asm volatile("mma.sync.aligned.m16n8k16.row.col.f32.bf16.bf16.f32 " \
    "{%0,%1,%2,%3},{%4,%5,%6,%7},{%8,%9},{%0,%1,%2,%3};" \
    : "+f"((C)[0]),"+f"((C)[1]),"+f"((C)[2]),"+f"((C)[3]) \
    : "r"((A)[0]),"r"((A)[1]),"r"((A)[2]),"r"((A)[3]),"r"((B)[0]),"r"((B)[1]))

__device__ __forceinline__ void cp16(bf16* s, const bf16* g) {
    uint32_t sa = (uint32_t)__cvta_generic_to_shared(s);
    asm volatile("cp.async.cg.shared.global [%0], [%1], 16;" :: "r"(sa), "l"(g));
}

__global__ __launch_bounds__(256, 1) void gemm_bf16s(
    const bf16* __restrict__ Ah, const bf16* __restrict__ Al,
    const bf16* __restrict__ Bh, const bf16* __restrict__ Bl,
    float* __restrict__ C, const float* __restrict__ RES,
    int K, int lda, int ldb, int ldc, float alpha,
    long sA, long sB, long sC, int bdiv)
{
    extern __shared__ bf16 sm[];
    int z = blockIdx.z;
    Ah += (long)z * sA;  Al += (long)z * sA;
    Bh += (long)(z / bdiv) * sB;  Bl += (long)(z / bdiv) * sB;
    C  += (long)z * sC;
    if (RES) RES += (long)z * sC;

    int tid = threadIdx.x;
    int bm = blockIdx.y * 128, bn = blockIdx.x * 128;

    // gmem->smem copy layout: 2 threads per row, 16 bf16 each
    int lrow = tid >> 1;
    int lch  = (tid & 1) << 4;
    const bf16* gAh = Ah + (long)(bm + lrow) * lda + lch;
    const bf16* gAl = Al + (long)(bm + lrow) * lda + lch;
    const bf16* gBh = Bh + (long)(bn + lrow) * ldb + lch;
    const bf16* gBl = Bl + (long)(bn + lrow) * ldb + lch;
    int soff = lrow * PAD + lch;

    int lane = tid & 31, wid = tid >> 5;
    int wm = wid >> 2, wn = wid & 3;

    // ldmatrix lane addressing
    int a_row = wm * 64 + (lane & 15);
    int a_col = (lane >> 4) << 3;
    int b_row = wn * 32 + (lane & 7) + ((lane >> 4) << 3);
    int b_col = lane & 8;

    float c[4][4][4];
#pragma unroll
    for (int i = 0; i < 4; i++)
#pragma unroll
        for (int j = 0; j < 4; j++)
#pragma unroll
            for (int e = 0; e < 4; e++) c[i][j][e] = 0.f;

    int nk = K >> 5;

    // prefetch stage 0
    {
        bf16* s = sm + soff;
        cp16(s + SA_H, gAh); cp16(s + SA_H + 8, gAh + 8);
        cp16(s + SA_L, gAl); cp16(s + SA_L + 8, gAl + 8);
        cp16(s + SB_H, gBh); cp16(s + SB_H + 8, gBh + 8);
        cp16(s + SB_L, gBl); cp16(s + SB_L + 8, gBl + 8);
    }
    asm volatile("cp.async.commit_group;");

    for (int kt = 0; kt < nk; kt++) {
        if (kt + 1 < nk) {
            int k0 = (kt + 1) << 5;
            bf16* s = sm + ((kt + 1) & 1) * STAGE_ELEMS + soff;
            cp16(s + SA_H, gAh + k0); cp16(s + SA_H + 8, gAh + k0 + 8);
            cp16(s + SA_L, gAl + k0); cp16(s + SA_L + 8, gAl + k0 + 8);
            cp16(s + SB_H, gBh + k0); cp16(s + SB_H + 8, gBh + k0 + 8);
            cp16(s + SB_L, gBl + k0); cp16(s + SB_L + 8, gBl + k0 + 8);
            asm volatile("cp.async.commit_group;");
            asm volatile("cp.async.wait_group 1;");
        } else {
            asm volatile("cp.async.wait_group 0;");
        }
        __syncthreads();

        uint32_t base = (uint32_t)__cvta_generic_to_shared(sm + (kt & 1) * STAGE_ELEMS);
#pragma unroll
        for (int ks = 0; ks < 2; ks++) {
            int kf = ks << 4;
            uint32_t ah[4][4], al[4][4], bh[4][2], bl[4][2];
#pragma unroll
            for (int mi = 0; mi < 4; mi++) {
                uint32_t ad = base + (uint32_t)(((a_row + mi * 16) * PAD + kf + a_col) * 2);
                LDSM4(ah[mi][0], ah[mi][1], ah[mi][2], ah[mi][3], ad + SA_H * 2);
                LDSM4(al[mi][0], al[mi][1], al[mi][2], al[mi][3], ad + SA_L * 2);
            }
#pragma unroll
            for (int nj = 0; nj < 2; nj++) {
                uint32_t bd = base + (uint32_t)(((b_row + nj * 16) * PAD + kf + b_col) * 2);
                uint32_t r0, r1, r2, r3;
                LDSM4(r0, r1, r2, r3, bd + SB_H * 2);
                bh[nj*2][0] = r0; bh[nj*2][1] = r1; bh[nj*2+1][0] = r2; bh[nj*2+1][1] = r3;
                LDSM4(r0, r1, r2, r3, bd + SB_L * 2);
                bl[nj*2][0] = r0; bl[nj*2][1] = r1; bl[nj*2+1][0] = r2; bl[nj*2+1][1] = r3;
            }
#pragma unroll
            for (int mi = 0; mi < 4; mi++)
#pragma unroll
                for (int ni = 0; ni < 4; ni++) {
                    MMA_B16(c[mi][ni], ah[mi], bh[ni]);
                    MMA_B16(c[mi][ni], ah[mi], bl[ni]);
                    MMA_B16(c[mi][ni], al[mi], bh[ni]);
                }
        }
        __syncthreads();
    }

    // epilogue
    int g = lane >> 2, t4 = lane & 3;
#pragma unroll
    for (int mi = 0; mi < 4; mi++) {
        long r0 = bm + wm * 64 + mi * 16 + g;
        long r1 = r0 + 8;
#pragma unroll
        for (int ni = 0; ni < 4; ni++) {
            long col = bn + wn * 32 + ni * 8 + t4 * 2;
            float2 v0, v1;
            v0.x = c[mi][ni][0] * alpha; v0.y = c[mi][ni][1] * alpha;
            v1.x = c[mi][ni][2] * alpha; v1.y = c[mi][ni][3] * alpha;
            if (RES) {
                float2 q0 = *(const float2*)(RES + r0 * ldc + col);
                float2 q1 = *(const float2*)(RES + r1 * ldc + col);
                v0.x += q0.x; v0.y += q0.y; v1.x += q1.x; v1.y += q1.y;
            }
            *(float2*)(C + r0 * ldc + col) = v0;
            *(float2*)(C + r1 * ldc + col) = v1;
        }
    }
}

// ---------------- pointwise kernels ----------------
__device__ __forceinline__ uint32_t pack2(bf16 a, bf16 b) {
    return (uint32_t)__bfloat16_as_ushort(a) | ((uint32_t)__bfloat16_as_ushort(b) << 16);
}

__global__ void split_k(const float* __restrict__ X, bf16* __restrict__ H,
                        bf16* __restrict__ L, long n)
{
    long i = ((long)blockIdx.x * 256 + threadIdx.x) * 4;
    if (i < n) {
        float4 v = *(const float4*)(X + i);
        bf16 h0, h1, h2, h3, l0, l1, l2, l3;
        split2(v.x, h0, l0); split2(v.y, h1, l1);
        split2(v.z, h2, l2); split2(v.w, h3, l3);
        uint2 hv; hv.x = pack2(h0, h1); hv.y = pack2(h2, h3);
        uint2 lv; lv.x = pack2(l0, l1); lv.y = pack2(l2, l3);
        *(uint2*)(H + i) = hv;
        *(uint2*)(L + i) = lv;
    }
}

__global__ void embed_k(const int* __restrict__ idx, const float* __restrict__ wte,
                        float* __restrict__ X)
{
    int t = blockIdx.x;
    int tok = idx[t];
    const float* src = wte + (long)tok * NE;
    for (int i = threadIdx.x; i < NE; i += 256)
        X[(long)t * NE + i] = src[i];
}

__global__ void rmsnorm_k(const float* __restrict__ X, const float* __restrict__ w,
                          bf16* __restrict__ H, bf16* __restrict__ L)
{
    int t = blockIdx.x;
    const float* x = X + (long)t * NE;
    float ss = 0.f;
    for (int i = threadIdx.x; i < NE; i += 256) { float v = x[i]; ss += v * v; }
    __shared__ float red[256];
    red[threadIdx.x] = ss; __syncthreads();
    for (int s = 128; s > 0; s >>= 1) {
        if (threadIdx.x < s) red[threadIdx.x] += red[threadIdx.x + s];
        __syncthreads();
    }
    float r = rsqrtf(red[0] / NE + 1e-5f);
    for (int i = threadIdx.x; i < NE; i += 256) {
        bf16 h, l; split2(x[i] * r * w[i], h, l);
        H[(long)t * NE + i] = h;
        L[(long)t * NE + i] = l;
    }
}

__global__ void rope_tab_k()
{
    int t = blockIdx.x, d = threadIdx.x;
    double theta = exp(-(double)d * (9.210340371976184 / 64.0));
    double a = (double)t * theta;
    g_cos[t * 64 + d] = (float)cos(a);
    g_sin[t * 64 + d] = (float)sin(a);
}

// RoPE + elu+1 with hi/lo split output.
__global__ void rope_elu_k(const float* __restrict__ QKV,
                           bf16* __restrict__ Qh, bf16* __restrict__ Ql,
                           bf16* __restrict__ Kh, bf16* __restrict__ Kl)
{
    int t = blockIdx.x;
    int u = blockIdx.y;
    int d = threadIdx.x;
    int gidx, slot;
    long off;
    bf16 *oh, *ol;
    if (u < NH) { gidx = u >> 2; slot = u & 3; off = ((long)u * T_SEQ + t) * HS; oh = Qh; ol = Ql; }
    else        { gidx = u - NH; slot = 4;     off = ((long)gidx * T_SEQ + t) * HS; oh = Kh; ol = Kl; }
    const float* src = QKV + (long)t * QKVD + (gidx * 6 + slot) * HS;
    float x1 = src[d], x2 = src[d + 64];
    float cc = g_cos[t * 64 + d], ss = g_sin[t * 64 + d];
    float o1 = x1 * cc - x2 * ss;
    float o2 = x1 * ss + x2 * cc;
    float e1 = (o1 > 0.f) ? o1 + 1.f : expf(o1);
    float e2 = (o2 > 0.f) ? o2 + 1.f : expf(o2);
    bf16 h, l;
    split2(e1, h, l); oh[off + d] = h;      ol[off + d] = l;
    split2(e2, h, l); oh[off + d + 64] = h; ol[off + d + 64] = l;
}

__global__ void copy_v_k(const float* __restrict__ QKV,
                         bf16* __restrict__ Vh, bf16* __restrict__ Vl)
{
    int t = blockIdx.x, g = blockIdx.y, d = threadIdx.x;
    float v = QKV[(long)t * QKVD + (g * 6 + 5) * HS + d];
    bf16 h, l; split2(v, h, l);
    long o = ((long)g * HS + d) * T_SEQ + t;
    Vh[o] = h; Vl[o] = l;
}

// masked row-normalize fp32 -> split bf16
__global__ void attn_norm_k(const float* __restrict__ S,
                            bf16* __restrict__ Sh, bf16* __restrict__ Sl)
{
    int t = blockIdx.x;
    int h = blockIdx.y;
    size_t base = (size_t)h * T_SEQ * T_SEQ + (size_t)t * T_SEQ;
    const float* row = S + base;
    float sum = 0.f;
    for (int s = threadIdx.x; s <= t; s += 256) sum += row[s];
    __shared__ float red[256];
    red[threadIdx.x] = sum; __syncthreads();
    for (int s = 128; s > 0; s >>= 1) {
        if (threadIdx.x < s) red[threadIdx.x] += red[threadIdx.x + s];
        __syncthreads();
    }
    float inv = 1.f / (red[0] + 1e-8f);
    for (int s = threadIdx.x; s < T_SEQ; s += 256) {
        float v = (s <= t) ? row[s] * inv : 0.f;
        bf16 hh, ll; split2(v, hh, ll);
        Sh[base + s] = hh; Sl[base + s] = ll;
    }
}

__global__ void silu_mul_k(const float* __restrict__ H1, const float* __restrict__ H2,
                           bf16* __restrict__ Hh, bf16* __restrict__ Hl)
{
    long i = (long)blockIdx.x * 256 + threadIdx.x;
    if (i < (long)T_SEQ * INTERD) {
        float a = H1[i];
        float v = (a / (1.f + expf(-a))) * H2[i];
        bf16 h, l; split2(v, h, l);
        Hh[i] = h; Hl[i] = l;
    }
}

// ---------------- driver ----------------
static void launch_gemm(const bf16* Ah, const bf16* Al, const bf16* Bh, const bf16* Bl,
                        float* C, const float* RES, int M, int N, int K,
                        int lda, int ldb, int ldc, float alpha,
                        long sA, long sB, long sC, int bdiv, int Z)
{
    gemm_bf16s<<<dim3(N / 128, M / 128, Z), 256, GEMM_SMEM>>>(
        Ah, Al, Bh, Bl, C, RES, K, lda, ldb, ldc, alpha, sA, sB, sC, bdiv);
}

static void launch_split(const float* X, bf16* H, bf16* L, long n)
{
    split_k<<<(int)((n + 1023) / 1024), 256>>>(X, H, L, n);
}

extern "C" void kernel_launch(void* const* d_in, const int* in_sizes, int n_in,
                              void* d_out, int out_size)
{
    const int*   idx      = (const int*)d_in[0];
    const float* wte      = (const float*)d_in[1];
    const float* attn_w   = (const float*)d_in[2];
    const float* proj_w   = (const float*)d_in[3];
    const float* w1       = (const float*)d_in[4];
    const float* w2       = (const float*)d_in[5];
    const float* w3       = (const float*)d_in[6];
    const float* norm1_w  = (const float*)d_in[7];
    const float* norm2_w  = (const float*)d_in[8];
    const float* ln_f_w   = (const float*)d_in[9];
    const float* lm_head  = (const float*)d_in[10];
    float* out = (float*)d_out;

    cudaFuncSetAttribute(gemm_bf16s, cudaFuncAttributeMaxDynamicSharedMemorySize, GEMM_SMEM);

    float *X, *QKV, *S, *Y, *H1, *H2;
    bf16 *Nh, *Nl, *Wh, *Wl, *Qh, *Ql, *Kh, *Kl, *Vh, *Vl, *Sh, *Sl, *Yh, *Yl, *Hh, *Hl;
    cudaGetSymbolAddress((void**)&X,   g_X);
    cudaGetSymbolAddress((void**)&QKV, g_QKV);
    cudaGetSymbolAddress((void**)&S,   g_S);
    cudaGetSymbolAddress((void**)&Y,   g_Y);
    cudaGetSymbolAddress((void**)&H1,  g_H1);
    cudaGetSymbolAddress((void**)&H2,  g_H2);
    cudaGetSymbolAddress((void**)&Nh,  g_Nh); cudaGetSymbolAddress((void**)&Nl, g_Nl);
    cudaGetSymbolAddress((void**)&Wh,  g_Wh); cudaGetSymbolAddress((void**)&Wl, g_Wl);
    cudaGetSymbolAddress((void**)&Qh,  g_Qh); cudaGetSymbolAddress((void**)&Ql, g_Ql);
    cudaGetSymbolAddress((void**)&Kh,  g_Kh); cudaGetSymbolAddress((void**)&Kl, g_Kl);
    cudaGetSymbolAddress((void**)&Vh,  g_Vh); cudaGetSymbolAddress((void**)&Vl, g_Vl);
    cudaGetSymbolAddress((void**)&Sh,  g_Sh); cudaGetSymbolAddress((void**)&Sl, g_Sl);
    cudaGetSymbolAddress((void**)&Yh,  g_Yh); cudaGetSymbolAddress((void**)&Yl, g_Yl);
    cudaGetSymbolAddress((void**)&Hh,  g_Hh); cudaGetSymbolAddress((void**)&Hl, g_Hl);

    const float scale = 1.f / sqrtf((float)HS);

    embed_k<<<T_SEQ, 256>>>(idx, wte, X);
    rope_tab_k<<<T_SEQ, 64>>>();

    for (int l = 0; l < 2; l++) {
        rmsnorm_k<<<T_SEQ, 256>>>(X, norm1_w + (long)l * NE, Nh, Nl);

        // qkv = n1 @ attn_w^T
        launch_split(attn_w + (long)l * QKVD * NE, Wh, Wl, (long)QKVD * NE);
        launch_gemm(Nh, Nl, Wh, Wl, QKV, nullptr, T_SEQ, QKVD, NE,
                    NE, NE, QKVD, 1.f, 0, 0, 0, 1, 1);

        rope_elu_k<<<dim3(T_SEQ, NH + NG), 64>>>(QKV, Qh, Ql, Kh, Kl);
        copy_v_k<<<dim3(T_SEQ, NG), 128>>>(QKV, Vh, Vl);

        // S[h] = scale * Q[h] @ K[h/4]^T
        launch_gemm(Qh, Ql, Kh, Kl, S, nullptr, T_SEQ, T_SEQ, HS,
                    HS, HS, T_SEQ, scale,
                    (long)T_SEQ * HS, (long)T_SEQ * HS, (long)T_SEQ * T_SEQ, 4, NH);

        attn_norm_k<<<dim3(T_SEQ, NH), 256>>>(S, Sh, Sl);

        // Y[:, h*128:(h+1)*128] = S[h] @ Vt[h/4]^T
        launch_gemm(Sh, Sl, Vh, Vl, Y, nullptr, T_SEQ, HS, T_SEQ,
                    T_SEQ, T_SEQ, NE, 1.f,
                    (long)T_SEQ * T_SEQ, (long)HS * T_SEQ, (long)HS, 4, NH);

        // X += Y @ proj^T
        launch_split(Y, Yh, Yl, (long)T_SEQ * NE);
        launch_split(proj_w + (long)l * NE * NE, Wh, Wl, (long)NE * NE);
        launch_gemm(Yh, Yl, Wh, Wl, X, X, T_SEQ, NE, NE,
                    NE, NE, NE, 1.f, 0, 0, 0, 1, 1);

        rmsnorm_k<<<T_SEQ, 256>>>(X, norm2_w + (long)l * NE, Nh, Nl);

        launch_split(w1 + (long)l * INTERD * NE, Wh, Wl, (long)INTERD * NE);
        launch_gemm(Nh, Nl, Wh, Wl, H1, nullptr, T_SEQ, INTERD, NE,
                    NE, NE, INTERD, 1.f, 0, 0, 0, 1, 1);
        launch_split(w2 + (long)l * INTERD * NE, Wh, Wl, (long)INTERD * NE);
        launch_gemm(Nh, Nl, Wh, Wl, H2, nullptr, T_SEQ, INTERD, NE,
                    NE, NE, INTERD, 1.f, 0, 0, 0, 1, 1);

        silu_mul_k<<<(int)(((long)T_SEQ * INTERD + 255) / 256), 256>>>(H1, H2, Hh, Hl);

        // X += H @ w3^T
        launch_split(w3 + (long)l * NE * INTERD, Wh, Wl, (long)NE * INTERD);
        launch_gemm(Hh, Hl, Wh, Wl, X, X, T_SEQ, NE, INTERD,
                    INTERD, INTERD, NE, 1.f, 0, 0, 0, 1, 1);
    }

    rmsnorm_k<<<T_SEQ, 256>>>(X, ln_f_w, Nh, Nl);

    // logits = x @ lm_head^T
    launch_split(lm_head, Wh, Wl, (long)VOCABN * NE);
    launch_gemm(Nh, Nl, Wh, Wl, out, nullptr, T_SEQ, VOCABN, NE,
                NE, NE, VOCABN, 1.f, 0, 0, 0, 1, 1);
}